// round 7
// baseline (speedup 1.0000x reference)
#include <cuda_runtime.h>
#include <cuda_bf16.h>
#include <cuda_fp16.h>
#include <cstdint>

#define H     4096
#define NIN   700
#define T     1000
#define NOUT  20

#define GEMM_M 1024          // T padded
#define GEMM_K 704           // NIN padded to 22*32
#define NBLK   8             // persistent blocks
#define NTHR   512           // threads per block (8*512 = 4096 = H)

// ---------------- device-global scratch (no cudaMalloc allowed) ----------------
__device__ signed char g_v1T[(size_t)H * H];      // v1 transposed int8: v1T[k][h] = v1[h][k]
__device__ signed char g_As8[GEMM_M * GEMM_K];    // spikes s8, padded [1024][704]
__device__ signed char g_Bs8[(size_t)H * GEMM_K]; // w1 s8, padded [4096][704]
__device__ int         g_inall[T * H];            // feed-forward currents
__device__ int         g_w2T[H * NOUT];           // w2 transposed int32: [k][o]
__device__ int         g_mask[2][H / 32];         // double-buffered spike bitmask (128 words)
__device__ unsigned    g_bar_arrive;              // software barrier (self-resetting)
__device__ unsigned    g_bar_gen;                 // generation counter (monotonic, replay-safe)
__device__ int         g_dt[4];                   // per-array dtype: 0 spk,1 w1,2 v1,3 w2
__device__ int         g_bad;                     // MMA verification flag

// dtype codes: 0:f32 1:i32 2:i64 3:f64 4:bf16 5:f16
__device__ __forceinline__ int ldin(const void* p, long idx, int dt) {
    switch (dt) {
        case 0:  return (int)((const float*)p)[idx];
        case 1:  return ((const int*)p)[idx];
        case 2:  return (int)((const long long*)p)[idx];
        case 3:  return (int)((const double*)p)[idx];
        case 4:  return (int)__bfloat162float(((const __nv_bfloat16*)p)[idx]);
        default: return (int)__half2float(((const __half*)p)[idx]);
    }
}

__device__ __forceinline__ bool bf16ok(unsigned short h) {  // bf16 of int in [-8,8] or 0
    unsigned short a = h & 0x7FFF;
    return h == 0 || a == 0x3F80 || a == 0x4000 || a == 0x4040 || a == 0x4080 ||
           a == 0x40A0 || a == 0x40C0 || a == 0x40E0 || a == 0x4100;
}
__device__ __forceinline__ bool f16ok(unsigned short h) {   // f16 of int in [-8,8] or 0
    unsigned short a = h & 0x7FFF;
    return h == 0 || a == 0x3C00 || a == 0x4000 || a == 0x4200 || a == 0x4400 ||
           a == 0x4500 || a == 0x4600 || a == 0x4700 || a == 0x4800;
}

__device__ int classify(const void* ptr) {
    const unsigned* p = (const unsigned*)ptr;
    const unsigned short* ph = (const unsigned short*)ptr;
    bool i64 = true;
    for (int i = 0; i < 32; i++) {
        int lo = (int)p[2 * i], hi = (int)p[2 * i + 1];
        bool sext = (hi == 0 && lo >= 0) || (hi == -1 && lo < 0);
        if (!(sext && lo >= -16 && lo <= 16)) { i64 = false; break; }
    }
    if (i64) return 2;
    bool f64 = true;
    for (int i = 0; i < 32; i++) {
        unsigned lo = p[2 * i], hi = p[2 * i + 1];
        unsigned ex = (hi >> 20) & 0x7FF;
        bool zero = (lo == 0 && (hi & 0x7FFFFFFFu) == 0);
        if (!(zero || (ex >= 1020 && ex <= 1026))) { f64 = false; break; }
    }
    if (f64) return 3;
    bool i32 = true;
    for (int i = 0; i < 64; i++) {
        int v = (int)p[i];
        if (v < -16 || v > 16) { i32 = false; break; }
    }
    if (i32) return 1;
    bool f32 = true;
    for (int i = 0; i < 64; i++) {
        if (!(ph[2 * i] == 0 && bf16ok(ph[2 * i + 1]))) { f32 = false; break; }
    }
    if (f32) return 0;
    bool b16 = true, anyEven = false;
    for (int i = 0; i < 128; i++) {
        if (!bf16ok(ph[i])) { b16 = false; break; }
        if ((i & 1) == 0 && ph[i] != 0) anyEven = true;
    }
    if (b16 && anyEven) return 4;
    bool h16 = true;
    for (int i = 0; i < 128; i++) if (!f16ok(ph[i])) { h16 = false; break; }
    if (h16) return 5;
    return 0;
}

// One thread: classify every input array independently.
__global__ void k_detect(const void* spk, const void* w1, const void* v1, const void* w2) {
    g_bad = 0;
    g_dt[0] = classify(spk);
    g_dt[1] = classify(w1);
    g_dt[2] = classify(v1);
    g_dt[3] = classify(w2);
}

// Pre-zero the output (float32) — finite baseline.
__global__ void k_zero_out(float* out) {
    int i = blockIdx.x * blockDim.x + threadIdx.x;
    if (i < NOUT * T) out[i] = 0.0f;
}

// ---------------- conversion kernels ----------------
// v1 [h][k] -> g_v1T [k][h] int8 via 32x32 smem tile transpose
__global__ void k_v1T(const void* v1) {
    __shared__ signed char tile[32][33];
    const int dt = g_dt[2];
    int k0 = blockIdx.x * 32, h0 = blockIdx.y * 32;
    int tx = threadIdx.x, ty = threadIdx.y;
    for (int r = ty; r < 32; r += 8)
        tile[tx][r] = (signed char)ldin(v1, (long)(h0 + r) * H + (k0 + tx), dt);
    __syncthreads();
    for (int r = ty; r < 32; r += 8)
        g_v1T[(size_t)(k0 + r) * H + (h0 + tx)] = tile[r][tx];
}

// spikes [1000][700] -> s8 [1024][704] (zero padded)
__global__ void k_packA(const void* spk) {
    int idx = blockIdx.x * blockDim.x + threadIdx.x;
    if (idx >= GEMM_M * GEMM_K) return;
    int t = idx / GEMM_K, i = idx % GEMM_K;
    int v = (t < T && i < NIN) ? ldin(spk, (long)t * NIN + i, g_dt[0]) : 0;
    g_As8[idx] = (signed char)v;
}

// w1 [4096][700] -> s8 [4096][704] (zero padded)
__global__ void k_packB(const void* w1) {
    int idx = blockIdx.x * blockDim.x + threadIdx.x;
    if (idx >= H * GEMM_K) return;
    int h = idx / GEMM_K, i = idx % GEMM_K;
    int v = (i < NIN) ? ldin(w1, (long)h * NIN + i, g_dt[1]) : 0;
    g_Bs8[idx] = (signed char)v;
}

// w2 [o][k] -> g_w2T[k][o]
__global__ void k_w2T(const void* w2) {
    int idx = blockIdx.x * blockDim.x + threadIdx.x;
    if (idx >= NOUT * H) return;
    int o = idx / H, k = idx % H;
    g_w2T[k * NOUT + o] = ldin(w2, (long)o * H + k, g_dt[3]);
}

// ---------------- int8 tensor-core GEMM: in_all[t][h] = sum_i spk[t][i]*w1[h][i] ----
__global__ void __launch_bounds__(256) k_gemm() {
    __shared__ signed char sA[64][32];
    __shared__ signed char sB[128][32];
    const int tid = threadIdx.x, lane = tid & 31, wid = tid >> 5;
    const int wm = wid & 1, wn = wid >> 1;
    const int mBase = blockIdx.y * 64, nBase = blockIdx.x * 128;

    int acc[2][4][4];
#pragma unroll
    for (int a = 0; a < 2; a++)
#pragma unroll
        for (int b = 0; b < 4; b++)
#pragma unroll
            for (int c = 0; c < 4; c++) acc[a][b][c] = 0;

    for (int k0 = 0; k0 < GEMM_K; k0 += 32) {
#pragma unroll
        for (int u = 0; u < 2; u++) {
            int w = tid + u * 256;
            int r = w >> 3, c = (w & 7) * 4;
            *(int*)&sA[r][c] = *(const int*)&g_As8[(mBase + r) * GEMM_K + k0 + c];
        }
#pragma unroll
        for (int u = 0; u < 4; u++) {
            int w = tid + u * 256;
            int r = w >> 3, c = (w & 7) * 4;
            *(int*)&sB[r][c] = *(const int*)&g_Bs8[(size_t)(nBase + r) * GEMM_K + k0 + c];
        }
        __syncthreads();

        int afrag[2][4];
#pragma unroll
        for (int mf = 0; mf < 2; mf++) {
            int r = wm * 32 + mf * 16 + (lane >> 2);
            int c = (lane & 3) * 4;
            afrag[mf][0] = *(const int*)&sA[r][c];
            afrag[mf][1] = *(const int*)&sA[r + 8][c];
            afrag[mf][2] = *(const int*)&sA[r][c + 16];
            afrag[mf][3] = *(const int*)&sA[r + 8][c + 16];
        }
        int bfrag[4][2];
#pragma unroll
        for (int nf = 0; nf < 4; nf++) {
            int col = wn * 32 + nf * 8 + (lane >> 2);
            int c = (lane & 3) * 4;
            bfrag[nf][0] = *(const int*)&sB[col][c];
            bfrag[nf][1] = *(const int*)&sB[col][c + 16];
        }
#pragma unroll
        for (int mf = 0; mf < 2; mf++)
#pragma unroll
            for (int nf = 0; nf < 4; nf++) {
                asm volatile(
                    "mma.sync.aligned.m16n8k32.row.col.s32.s8.s8.s32 "
                    "{%0,%1,%2,%3}, {%4,%5,%6,%7}, {%8,%9}, {%0,%1,%2,%3};"
                    : "+r"(acc[mf][nf][0]), "+r"(acc[mf][nf][1]),
                      "+r"(acc[mf][nf][2]), "+r"(acc[mf][nf][3])
                    : "r"(afrag[mf][0]), "r"(afrag[mf][1]),
                      "r"(afrag[mf][2]), "r"(afrag[mf][3]),
                      "r"(bfrag[nf][0]), "r"(bfrag[nf][1]));
            }
        __syncthreads();
    }
#pragma unroll
    for (int mf = 0; mf < 2; mf++) {
        int r0 = mBase + wm * 32 + mf * 16 + (lane >> 2);
#pragma unroll
        for (int nf = 0; nf < 4; nf++) {
            int c0 = nBase + wn * 32 + nf * 8 + (lane & 3) * 2;
            if (r0 < T) {
                g_inall[r0 * H + c0]     = acc[mf][nf][0];
                g_inall[r0 * H + c0 + 1] = acc[mf][nf][1];
            }
            if (r0 + 8 < T) {
                g_inall[(r0 + 8) * H + c0]     = acc[mf][nf][2];
                g_inall[(r0 + 8) * H + c0 + 1] = acc[mf][nf][3];
            }
        }
    }
}

// Verify 4096 scattered elements of g_inall via scalar dp4a.
__global__ void k_gemm_check() {
    int idx = blockIdx.x * blockDim.x + threadIdx.x;
    int t = (idx * 61) % T;
    int h = (idx * 97) % H;
    int acc = 0;
    for (int j = 0; j < GEMM_K / 4; j++)
        acc = __dp4a(*(const int*)&g_As8[t * GEMM_K + 4 * j],
                     *(const int*)&g_Bs8[(size_t)h * GEMM_K + 4 * j], acc);
    if (acc != g_inall[t * H + h]) g_bad = 1;
}

// Fallback: full dp4a recompute if the MMA result was wrong.
__global__ void k_gemm_fix() {
    if (g_bad == 0) return;
    int base = (blockIdx.x * blockDim.x + threadIdx.x) * 4;
    for (int e = 0; e < 4; e++) {
        int idx = base + e;
        if (idx >= T * H) return;
        int t = idx / H, h = idx % H;
        int acc = 0;
        for (int j = 0; j < GEMM_K / 4; j++)
            acc = __dp4a(*(const int*)&g_As8[t * GEMM_K + 4 * j],
                         *(const int*)&g_Bs8[(size_t)h * GEMM_K + 4 * j], acc);
        g_inall[idx] = acc;
    }
}

// ---------------- memory-order helpers ----------------
__device__ __forceinline__ unsigned atomAddAcqRel(unsigned* p, unsigned v) {
    unsigned old;
    asm volatile("atom.acq_rel.gpu.add.u32 %0, [%1], %2;" : "=r"(old) : "l"(p), "r"(v) : "memory");
    return old;
}
__device__ __forceinline__ unsigned ldAcqU(unsigned* p) {
    unsigned v;
    asm volatile("ld.acquire.gpu.u32 %0, [%1];" : "=r"(v) : "l"(p) : "memory");
    return v;
}
__device__ __forceinline__ int ldAcqI(const int* p) {
    int v;
    asm volatile("ld.acquire.gpu.s32 %0, [%1];" : "=r"(v) : "l"(p) : "memory");
    return v;
}
__device__ __forceinline__ void stRel(unsigned* p, unsigned v) {
    asm volatile("st.release.gpu.u32 [%0], %1;" :: "l"(p), "r"(v) : "memory");
}
__device__ __forceinline__ void gridBarrier(unsigned& myGen) {
    __threadfence();
    __syncthreads();
    if (threadIdx.x == 0) {
        myGen++;
        unsigned a = atomAddAcqRel(&g_bar_arrive, 1u);
        if (a == NBLK - 1) {
            stRel(&g_bar_arrive, 0u);
            atomAddAcqRel(&g_bar_gen, 1u);
        } else {
            while (ldAcqU(&g_bar_gen) != myGen) { }
        }
    }
    __syncthreads();
}

// ---------------- persistent recurrent loop: 8 blocks x 512 threads ----------------
// Spike exchange via double-buffered ballot bitmask: fully deterministic, no atomics.
__global__ void __launch_bounds__(NTHR, 1) k_snn(float* __restrict__ rout) {
    __shared__ int sList[H];
    __shared__ int sMask[H / 32];      // 128 words
    __shared__ int sBase[H / 32 + 1];  // exclusive bases + total
    const int tid = threadIdx.x;
    const int cta = blockIdx.x;
    const int gid = cta * NTHR + tid;  // one hidden neuron per thread
    int mem = 0, syn = 0, prevOut = 0;
    int rmem = 0, rsyn = 0;

    unsigned myGen = 0;
    if (tid == 0) myGen = ldAcqU(&g_bar_gen);     // replay-safe base
    if (cta == 0 && tid < H / 32) g_mask[1][tid] = 0;   // S_{-1} = empty
    gridBarrier(myGen);

    for (int t = 0; t < T; t++) {
        const int inc = g_inall[t * H + gid];     // immutable prefetch

        // 1) spike decision from carried local state (reset -> threshold)
        const int m0 = prevOut ? 0 : mem;
        const int o = (m0 - 1 > 0) ? 1 : 0;
        prevOut = o;

        // 2) publish S_t: warp ballot -> one plain store per warp (full overwrite)
        unsigned ball = __ballot_sync(0xffffffffu, o);
        if ((tid & 31) == 0) g_mask[t & 1][gid >> 5] = (int)ball;

        // 3) read S_{t-1} mask (written last step; grid barrier between)
        if (tid < H / 32) sMask[tid] = ldAcqI(&g_mask[(t + 1) & 1][tid]);
        __syncthreads();

        // 4) prefix-scan popcounts (warp 0), then emit index list
        if (tid < 32) {
            int c0 = __popc(sMask[4 * tid + 0]);
            int c1 = __popc(sMask[4 * tid + 1]);
            int c2 = __popc(sMask[4 * tid + 2]);
            int c3 = __popc(sMask[4 * tid + 3]);
            int s = c0 + c1 + c2 + c3;
            int incl = s;
#pragma unroll
            for (int d = 1; d < 32; d <<= 1) {
                int v = __shfl_up_sync(0xffffffffu, incl, d);
                if (tid >= d) incl += v;
            }
            int excl = incl - s;
            sBase[4 * tid + 0] = excl;
            sBase[4 * tid + 1] = excl + c0;
            sBase[4 * tid + 2] = excl + c0 + c1;
            sBase[4 * tid + 3] = excl + c0 + c1 + c2;
            if (tid == 31) sBase[H / 32] = incl;  // total K
        }
        __syncthreads();
        const int K = sBase[H / 32];
        if (tid < H / 32) {
            unsigned m = (unsigned)sMask[tid];
            int b = sBase[tid];
            int base_idx = tid << 5;
            while (m) {
                int p = __ffs(m) - 1;
                sList[b++] = base_idx + p;
                m &= m - 1;
            }
        }
        __syncthreads();

        // 5) recurrent feedback gather: fb[h] = sum_{k in S_{t-1}} v1[h][k]
        int fb = 0;
        int j = 0;
        for (; j + 4 <= K; j += 4) {
            int i0 = sList[j], i1 = sList[j + 1], i2 = sList[j + 2], i3 = sList[j + 3];
            fb += (int)g_v1T[((size_t)i0 << 12) + gid];
            fb += (int)g_v1T[((size_t)i1 << 12) + gid];
            fb += (int)g_v1T[((size_t)i2 << 12) + gid];
            fb += (int)g_v1T[((size_t)i3 << 12) + gid];
        }
        for (; j < K; j++) fb += (int)g_v1T[((size_t)sList[j] << 12) + gid];

        // 6) LIF state update (exact int32; all BW64 saturations are no-ops)
        mem = m0 - (m0 >> 3) + syn;
        syn = syn - (syn >> 4) + (inc + fb);

        // 7) readout (block 0): rsyn'_t = decay(rsyn'_{t-1}) + w2 @ S_{t-1};
        //    rmem_t = decay(rmem_{t-1}) + rsyn'_t   (== reference recorded value)
        if (cta == 0 && tid < NOUT) {
            int rc = 0;
            for (int jj = 0; jj < K; jj++) rc += g_w2T[sList[jj] * NOUT + tid];
            rsyn = rsyn - (rsyn >> 4) + rc;
            rmem = rmem - (rmem >> 3) + rsyn;
            rout[tid * T + t] = (float)rmem;      // OUTPUT = float32, exact (<2^24)
        }

        // 8) grid-wide barrier
        gridBarrier(myGen);
    }
}

// ---------------- launch ----------------
extern "C" void kernel_launch(void* const* d_in, const int* in_sizes, int n_in,
                              void* d_out, int out_size) {
    // identify inputs by element count (fallback: metadata order), bytes-tolerant
    const void *spk = d_in[0], *w1 = d_in[1], *v1 = d_in[2], *w2 = d_in[3];
    for (int i = 0; i < n_in; i++) {
        long s = in_sizes[i];
        if (s == (long)T * NIN || s == 4L * T * NIN || s == 8L * T * NIN || s == 2L * T * NIN)
            spk = d_in[i];
        else if (s == (long)H * NIN || s == 4L * H * NIN || s == 8L * H * NIN || s == 2L * H * NIN)
            w1 = d_in[i];
        else if (s == (long)H * H || s == 4L * H * H || s == 8L * H * H || s == 2L * H * H)
            v1 = d_in[i];
        else if (s == (long)NOUT * H || s == 4L * NOUT * H || s == 8L * NOUT * H || s == 2L * NOUT * H)
            w2 = d_in[i];
    }
    (void)out_size;

    k_detect<<<1, 1>>>(spk, w1, v1, w2);
    k_zero_out<<<(NOUT * T + 255) / 256, 256>>>((float*)d_out);
    k_v1T<<<dim3(H / 32, H / 32), dim3(32, 8)>>>(v1);
    k_packA<<<(GEMM_M * GEMM_K + 255) / 256, 256>>>(spk);
    k_packB<<<(H * GEMM_K + 255) / 256, 256>>>(w1);
    k_w2T<<<(NOUT * H + 255) / 256, 256>>>(w2);
    k_gemm<<<dim3(H / 128, GEMM_M / 64), 256>>>();
    k_gemm_check<<<16, 256>>>();
    k_gemm_fix<<<(T * H / 4 + 255) / 256, 256>>>();
    k_snn<<<NBLK, NTHR>>>((float*)d_out);
}

// round 9
// speedup vs baseline: 1.4443x; 1.4443x over previous
#include <cuda_runtime.h>
#include <cuda_bf16.h>
#include <cuda_fp16.h>
#include <cstdint>

#define H     4096
#define NIN   700
#define T     1000
#define NOUT  20

#define GEMM_M 1024          // T padded
#define GEMM_K 704           // NIN padded to 22*32
#define NBLK   8             // persistent blocks
#define NTHR   512           // threads per block (8*512 = 4096 = H)

// ---------------- device-global scratch (no cudaMalloc allowed) ----------------
__device__ signed char g_v1T[(size_t)H * H];      // v1 transposed int8: v1T[k][h] = v1[h][k]
__device__ signed char g_As8[GEMM_M * GEMM_K];    // spikes s8, padded [1024][704]
__device__ signed char g_Bs8[(size_t)H * GEMM_K]; // w1 s8, padded [4096][704]
__device__ int         g_inall[T * H];            // feed-forward currents
__device__ int         g_w2T[H * NOUT];           // w2 transposed int32: [k][o]
__device__ int         g_mask[6][H / 32];         // 6-slot ring of spike bitmasks
__device__ unsigned    g_bar_arrive;              // software barrier (self-resetting)
__device__ unsigned    g_bar_gen;                 // generation counter (monotonic, replay-safe)
__device__ int         g_dt[4];                   // per-array dtype: 0 spk,1 w1,2 v1,3 w2
__device__ int         g_bad;                     // MMA verification flag

// dtype codes: 0:f32 1:i32 2:i64 3:f64 4:bf16 5:f16
__device__ __forceinline__ int ldin(const void* p, long idx, int dt) {
    switch (dt) {
        case 0:  return (int)((const float*)p)[idx];
        case 1:  return ((const int*)p)[idx];
        case 2:  return (int)((const long long*)p)[idx];
        case 3:  return (int)((const double*)p)[idx];
        case 4:  return (int)__bfloat162float(((const __nv_bfloat16*)p)[idx]);
        default: return (int)__half2float(((const __half*)p)[idx]);
    }
}

__device__ __forceinline__ bool bf16ok(unsigned short h) {
    unsigned short a = h & 0x7FFF;
    return h == 0 || a == 0x3F80 || a == 0x4000 || a == 0x4040 || a == 0x4080 ||
           a == 0x40A0 || a == 0x40C0 || a == 0x40E0 || a == 0x4100;
}
__device__ __forceinline__ bool f16ok(unsigned short h) {
    unsigned short a = h & 0x7FFF;
    return h == 0 || a == 0x3C00 || a == 0x4000 || a == 0x4200 || a == 0x4400 ||
           a == 0x4500 || a == 0x4600 || a == 0x4700 || a == 0x4800;
}

__device__ int classify(const void* ptr) {
    const unsigned* p = (const unsigned*)ptr;
    const unsigned short* ph = (const unsigned short*)ptr;
    bool i64 = true;
    for (int i = 0; i < 32; i++) {
        int lo = (int)p[2 * i], hi = (int)p[2 * i + 1];
        bool sext = (hi == 0 && lo >= 0) || (hi == -1 && lo < 0);
        if (!(sext && lo >= -16 && lo <= 16)) { i64 = false; break; }
    }
    if (i64) return 2;
    bool f64 = true;
    for (int i = 0; i < 32; i++) {
        unsigned lo = p[2 * i], hi = p[2 * i + 1];
        unsigned ex = (hi >> 20) & 0x7FF;
        bool zero = (lo == 0 && (hi & 0x7FFFFFFFu) == 0);
        if (!(zero || (ex >= 1020 && ex <= 1026))) { f64 = false; break; }
    }
    if (f64) return 3;
    bool i32 = true;
    for (int i = 0; i < 64; i++) {
        int v = (int)p[i];
        if (v < -16 || v > 16) { i32 = false; break; }
    }
    if (i32) return 1;
    bool f32 = true;
    for (int i = 0; i < 64; i++) {
        if (!(ph[2 * i] == 0 && bf16ok(ph[2 * i + 1]))) { f32 = false; break; }
    }
    if (f32) return 0;
    bool b16 = true, anyEven = false;
    for (int i = 0; i < 128; i++) {
        if (!bf16ok(ph[i])) { b16 = false; break; }
        if ((i & 1) == 0 && ph[i] != 0) anyEven = true;
    }
    if (b16 && anyEven) return 4;
    bool h16 = true;
    for (int i = 0; i < 128; i++) if (!f16ok(ph[i])) { h16 = false; break; }
    if (h16) return 5;
    return 0;
}

__global__ void k_detect(const void* spk, const void* w1, const void* v1, const void* w2) {
    g_bad = 0;
    g_dt[0] = classify(spk);
    g_dt[1] = classify(w1);
    g_dt[2] = classify(v1);
    g_dt[3] = classify(w2);
}

__global__ void k_zero_out(float* out) {
    int i = blockIdx.x * blockDim.x + threadIdx.x;
    if (i < NOUT * T) out[i] = 0.0f;
}

// ---------------- conversion kernels ----------------
__global__ void k_v1T(const void* v1) {
    __shared__ signed char tile[32][33];
    const int dt = g_dt[2];
    int k0 = blockIdx.x * 32, h0 = blockIdx.y * 32;
    int tx = threadIdx.x, ty = threadIdx.y;
    for (int r = ty; r < 32; r += 8)
        tile[tx][r] = (signed char)ldin(v1, (long)(h0 + r) * H + (k0 + tx), dt);
    __syncthreads();
    for (int r = ty; r < 32; r += 8)
        g_v1T[(size_t)(k0 + r) * H + (h0 + tx)] = tile[r][tx];
}

__global__ void k_packA(const void* spk) {
    int idx = blockIdx.x * blockDim.x + threadIdx.x;
    if (idx >= GEMM_M * GEMM_K) return;
    int t = idx / GEMM_K, i = idx % GEMM_K;
    int v = (t < T && i < NIN) ? ldin(spk, (long)t * NIN + i, g_dt[0]) : 0;
    g_As8[idx] = (signed char)v;
}

__global__ void k_packB(const void* w1) {
    int idx = blockIdx.x * blockDim.x + threadIdx.x;
    if (idx >= H * GEMM_K) return;
    int h = idx / GEMM_K, i = idx % GEMM_K;
    int v = (i < NIN) ? ldin(w1, (long)h * NIN + i, g_dt[1]) : 0;
    g_Bs8[idx] = (signed char)v;
}

__global__ void k_w2T(const void* w2) {
    int idx = blockIdx.x * blockDim.x + threadIdx.x;
    if (idx >= NOUT * H) return;
    int o = idx / H, k = idx % H;
    g_w2T[k * NOUT + o] = ldin(w2, (long)o * H + k, g_dt[3]);
}

// ---------------- int8 tensor-core GEMM ----------------
__global__ void __launch_bounds__(256) k_gemm() {
    __shared__ signed char sA[64][32];
    __shared__ signed char sB[128][32];
    const int tid = threadIdx.x, lane = tid & 31, wid = tid >> 5;
    const int wm = wid & 1, wn = wid >> 1;
    const int mBase = blockIdx.y * 64, nBase = blockIdx.x * 128;

    int acc[2][4][4];
#pragma unroll
    for (int a = 0; a < 2; a++)
#pragma unroll
        for (int b = 0; b < 4; b++)
#pragma unroll
            for (int c = 0; c < 4; c++) acc[a][b][c] = 0;

    for (int k0 = 0; k0 < GEMM_K; k0 += 32) {
#pragma unroll
        for (int u = 0; u < 2; u++) {
            int w = tid + u * 256;
            int r = w >> 3, c = (w & 7) * 4;
            *(int*)&sA[r][c] = *(const int*)&g_As8[(mBase + r) * GEMM_K + k0 + c];
        }
#pragma unroll
        for (int u = 0; u < 4; u++) {
            int w = tid + u * 256;
            int r = w >> 3, c = (w & 7) * 4;
            *(int*)&sB[r][c] = *(const int*)&g_Bs8[(size_t)(nBase + r) * GEMM_K + k0 + c];
        }
        __syncthreads();

        int afrag[2][4];
#pragma unroll
        for (int mf = 0; mf < 2; mf++) {
            int r = wm * 32 + mf * 16 + (lane >> 2);
            int c = (lane & 3) * 4;
            afrag[mf][0] = *(const int*)&sA[r][c];
            afrag[mf][1] = *(const int*)&sA[r + 8][c];
            afrag[mf][2] = *(const int*)&sA[r][c + 16];
            afrag[mf][3] = *(const int*)&sA[r + 8][c + 16];
        }
        int bfrag[4][2];
#pragma unroll
        for (int nf = 0; nf < 4; nf++) {
            int col = wn * 32 + nf * 8 + (lane >> 2);
            int c = (lane & 3) * 4;
            bfrag[nf][0] = *(const int*)&sB[col][c];
            bfrag[nf][1] = *(const int*)&sB[col][c + 16];
        }
#pragma unroll
        for (int mf = 0; mf < 2; mf++)
#pragma unroll
            for (int nf = 0; nf < 4; nf++) {
                asm volatile(
                    "mma.sync.aligned.m16n8k32.row.col.s32.s8.s8.s32 "
                    "{%0,%1,%2,%3}, {%4,%5,%6,%7}, {%8,%9}, {%0,%1,%2,%3};"
                    : "+r"(acc[mf][nf][0]), "+r"(acc[mf][nf][1]),
                      "+r"(acc[mf][nf][2]), "+r"(acc[mf][nf][3])
                    : "r"(afrag[mf][0]), "r"(afrag[mf][1]),
                      "r"(afrag[mf][2]), "r"(afrag[mf][3]),
                      "r"(bfrag[nf][0]), "r"(bfrag[nf][1]));
            }
        __syncthreads();
    }
#pragma unroll
    for (int mf = 0; mf < 2; mf++) {
        int r0 = mBase + wm * 32 + mf * 16 + (lane >> 2);
#pragma unroll
        for (int nf = 0; nf < 4; nf++) {
            int c0 = nBase + wn * 32 + nf * 8 + (lane & 3) * 2;
            if (r0 < T) {
                g_inall[r0 * H + c0]     = acc[mf][nf][0];
                g_inall[r0 * H + c0 + 1] = acc[mf][nf][1];
            }
            if (r0 + 8 < T) {
                g_inall[(r0 + 8) * H + c0]     = acc[mf][nf][2];
                g_inall[(r0 + 8) * H + c0 + 1] = acc[mf][nf][3];
            }
        }
    }
}

__global__ void k_gemm_check() {
    int idx = blockIdx.x * blockDim.x + threadIdx.x;
    int t = (idx * 61) % T;
    int h = (idx * 97) % H;
    int acc = 0;
    for (int j = 0; j < GEMM_K / 4; j++)
        acc = __dp4a(*(const int*)&g_As8[t * GEMM_K + 4 * j],
                     *(const int*)&g_Bs8[(size_t)h * GEMM_K + 4 * j], acc);
    if (acc != g_inall[t * H + h]) g_bad = 1;
}

__global__ void k_gemm_fix() {
    if (g_bad == 0) return;
    int base = (blockIdx.x * blockDim.x + threadIdx.x) * 4;
    for (int e = 0; e < 4; e++) {
        int idx = base + e;
        if (idx >= T * H) return;
        int t = idx / H, h = idx % H;
        int acc = 0;
        for (int j = 0; j < GEMM_K / 4; j++)
            acc = __dp4a(*(const int*)&g_As8[t * GEMM_K + 4 * j],
                         *(const int*)&g_Bs8[(size_t)h * GEMM_K + 4 * j], acc);
        g_inall[idx] = acc;
    }
}

// ---------------- memory-order helpers ----------------
__device__ __forceinline__ unsigned atomAddAcqRel(unsigned* p, unsigned v) {
    unsigned old;
    asm volatile("atom.acq_rel.gpu.add.u32 %0, [%1], %2;" : "=r"(old) : "l"(p), "r"(v) : "memory");
    return old;
}
__device__ __forceinline__ unsigned ldAcqU(unsigned* p) {
    unsigned v;
    asm volatile("ld.acquire.gpu.u32 %0, [%1];" : "=r"(v) : "l"(p) : "memory");
    return v;
}
__device__ __forceinline__ int ldAcqI(const int* p) {
    int v;
    asm volatile("ld.acquire.gpu.s32 %0, [%1];" : "=r"(v) : "l"(p) : "memory");
    return v;
}
__device__ __forceinline__ void stRel(unsigned* p, unsigned v) {
    asm volatile("st.release.gpu.u32 [%0], %1;" :: "l"(p), "r"(v) : "memory");
}
// Barrier WITHOUT per-thread fences: producers fence individually before arriving.
__device__ __forceinline__ void gridBarrier(unsigned& myGen) {
    __syncthreads();
    if (threadIdx.x == 0) {
        myGen++;
        unsigned a = atomAddAcqRel(&g_bar_arrive, 1u);
        if (a == NBLK - 1) {
            stRel(&g_bar_arrive, 0u);
            atomAddAcqRel(&g_bar_gen, 1u);
        } else {
            while (ldAcqU(&g_bar_gen) != myGen) {
                __nanosleep(64);      // ease L2 pressure while spinning
            }
        }
    }
    __syncthreads();
}

// warp-collective: scan popcounts of 128 mask words -> exclusive bases + total
__device__ __forceinline__ void scan128(const int* m, int* b, int lane) {
    int c0 = __popc(m[4 * lane + 0]);
    int c1 = __popc(m[4 * lane + 1]);
    int c2 = __popc(m[4 * lane + 2]);
    int c3 = __popc(m[4 * lane + 3]);
    int s = c0 + c1 + c2 + c3;
    int incl = s;
#pragma unroll
    for (int d = 1; d < 32; d <<= 1) {
        int v = __shfl_up_sync(0xffffffffu, incl, d);
        if (lane >= d) incl += v;
    }
    int excl = incl - s;
    b[4 * lane + 0] = excl;
    b[4 * lane + 1] = excl + c0;
    b[4 * lane + 2] = excl + c0 + c1;
    b[4 * lane + 3] = excl + c0 + c1 + c2;
    if (lane == 31) b[128] = incl;
}

__device__ __forceinline__ void buildList(const int* m, const int* b, int* list, int w) {
    unsigned mk = (unsigned)m[w];
    int p = b[w];
    int base = w << 5;
    while (mk) {
        int bit = __ffs(mk) - 1;
        list[p++] = base + bit;
        mk &= mk - 1;
    }
}

// ---------------- persistent recurrent loop: 3 steps per grid barrier ----------------
// Dependency depth: o_t depends on S_{t-3}; so with S_{<=t-1} known, spikes
// o_t, o_{t+1}, o_{t+2} are all computable pre-barrier (only fb_t <- S_{t-1} needed).
__global__ void __launch_bounds__(NTHR, 1) k_snn(float* __restrict__ rout) {
    __shared__ int sM0[128], sM1[128], sM2[128];
    __shared__ int sB0[129], sB1[129], sB2[129];
    __shared__ int sL[2][H];          // 32 KB
    const int tid = threadIdx.x;
    const int cta = blockIdx.x;
    const int gid = cta * NTHR + tid;
    int mem = 0, syn = 0, po = 0;
    int rmem = 0, rsyn = 0;

    unsigned myGen = 0;
    if (tid == 0) myGen = ldAcqU(&g_bar_gen);
    if (tid < 128) {                  // all blocks write zeros (same value: benign)
#pragma unroll
        for (int s = 0; s < 6; s++) g_mask[s][tid] = 0;
        __threadfence();
    }
    gridBarrier(myGen);

    for (int t = 0; t < 1002; t += 3) {         // 334 phases x 3 steps (last 2 padded)
        const int inc0 = g_inall[t * H + gid];  // t <= 999 always
        const int inc1 = (t + 1 < T) ? g_inall[(t + 1) * H + gid] : 0;
        const int inc2 = (t + 2 < T) ? g_inall[(t + 2) * H + gid] : 0;

        // ---- pre-barrier: S_{t-1} -> fb_t; compute & publish o_t, o_{t+1}, o_{t+2} ----
        if (tid < 128) sM0[tid] = ldAcqI(&g_mask[(t + 5) % 6][tid]);
        __syncthreads();
        if (tid < 32) scan128(sM0, sB0, tid);
        __syncthreads();
        if (tid < 128) buildList(sM0, sB0, sL[0], tid);
        __syncthreads();
        const int K0 = sB0[128];

        int fb0 = 0;
        {
            int j = 0;
            for (; j + 4 <= K0; j += 4) {
                int i0 = sL[0][j], i1 = sL[0][j + 1], i2 = sL[0][j + 2], i3 = sL[0][j + 3];
                fb0 += (int)g_v1T[((size_t)i0 << 12) + gid];
                fb0 += (int)g_v1T[((size_t)i1 << 12) + gid];
                fb0 += (int)g_v1T[((size_t)i2 << 12) + gid];
                fb0 += (int)g_v1T[((size_t)i3 << 12) + gid];
            }
            for (; j < K0; j++) fb0 += (int)g_v1T[((size_t)sL[0][j] << 12) + gid];
        }

        const int m0 = po ? 0 : mem;
        const int o0 = (m0 > 1) ? 1 : 0;
        const int mt = m0 - (m0 >> 3) + syn;           // mem_t
        const int st = syn - (syn >> 4) + inc0 + fb0;  // syn_t
        const int m1 = o0 ? 0 : mt;
        const int o1 = (m1 > 1) ? 1 : 0;
        const int mt1 = m1 - (m1 >> 3) + st;           // mem_{t+1}
        const int m2 = o1 ? 0 : mt1;
        const int o2 = (m2 > 1) ? 1 : 0;

        unsigned b0 = __ballot_sync(0xffffffffu, o0);
        unsigned b1 = __ballot_sync(0xffffffffu, o1);
        unsigned b2 = __ballot_sync(0xffffffffu, o2);
        if ((tid & 31) == 0) {
            g_mask[t % 6][gid >> 5]       = (int)b0;
            g_mask[(t + 1) % 6][gid >> 5] = (int)b1;
            g_mask[(t + 2) % 6][gid >> 5] = (int)b2;
            __threadfence();   // producer-side fence (16 threads/block, not 512)
        }

        // readout step t (uses S_{t-1} = L0) — overlaps with other warps' work
        if (cta == 0 && tid < NOUT) {
            int rc = 0;
            for (int j = 0; j < K0; j++) rc += g_w2T[sL[0][j] * NOUT + tid];
            rsyn = rsyn - (rsyn >> 4) + rc;
            rmem = rmem - (rmem >> 3) + rsyn;
            rout[tid * T + t] = (float)rmem;           // t <= 999
        }

        gridBarrier(myGen);

        // ---- post-barrier: S_t, S_{t+1} -> fb_{t+1}, fb_{t+2} (fused gathers) ----
        if (tid < 128) sM1[tid] = ldAcqI(&g_mask[t % 6][tid]);
        else if (tid < 256) sM2[tid - 128] = ldAcqI(&g_mask[(t + 1) % 6][tid - 128]);
        __syncthreads();
        if (tid < 32) scan128(sM1, sB1, tid);
        else if (tid >= 128 && tid < 160) scan128(sM2, sB2, tid - 128);
        __syncthreads();
        if (tid < 128) buildList(sM1, sB1, sL[0], tid);
        else if (tid < 256) buildList(sM2, sB2, sL[1], tid - 128);
        __syncthreads();
        const int K1 = sB1[128], K2 = sB2[128];

        int fb1 = 0, fb2 = 0;
        const int KM = K1 > K2 ? K1 : K2;
#pragma unroll 2
        for (int j = 0; j < KM; j++) {
            if (j < K1) fb1 += (int)g_v1T[((size_t)sL[0][j] << 12) + gid];
            if (j < K2) fb2 += (int)g_v1T[((size_t)sL[1][j] << 12) + gid];
        }

        const int st1 = st - (st >> 4) + inc1 + fb1;   // syn_{t+1}
        const int mt2 = m2 - (m2 >> 3) + st1;          // mem_{t+2}
        const int st2 = st1 - (st1 >> 4) + inc2 + fb2; // syn_{t+2}
        mem = mt2; syn = st2; po = o2;

        if (cta == 0 && tid < NOUT) {
            int rc1 = 0, rc2 = 0;
            for (int j = 0; j < K1; j++) rc1 += g_w2T[sL[0][j] * NOUT + tid];
            for (int j = 0; j < K2; j++) rc2 += g_w2T[sL[1][j] * NOUT + tid];
            rsyn = rsyn - (rsyn >> 4) + rc1;
            rmem = rmem - (rmem >> 3) + rsyn;
            if (t + 1 < T) rout[tid * T + t + 1] = (float)rmem;
            rsyn = rsyn - (rsyn >> 4) + rc2;
            rmem = rmem - (rmem >> 3) + rsyn;
            if (t + 2 < T) rout[tid * T + t + 2] = (float)rmem;
        }
        // no trailing barrier: next phase's reads/writes are separated by this
        // phase's mid barrier (6-slot ring gives >=1 barrier between conflicts)
    }
}

// ---------------- launch ----------------
extern "C" void kernel_launch(void* const* d_in, const int* in_sizes, int n_in,
                              void* d_out, int out_size) {
    const void *spk = d_in[0], *w1 = d_in[1], *v1 = d_in[2], *w2 = d_in[3];
    for (int i = 0; i < n_in; i++) {
        long s = in_sizes[i];
        if (s == (long)T * NIN || s == 4L * T * NIN || s == 8L * T * NIN || s == 2L * T * NIN)
            spk = d_in[i];
        else if (s == (long)H * NIN || s == 4L * H * NIN || s == 8L * H * NIN || s == 2L * H * NIN)
            w1 = d_in[i];
        else if (s == (long)H * H || s == 4L * H * H || s == 8L * H * H || s == 2L * H * H)
            v1 = d_in[i];
        else if (s == (long)NOUT * H || s == 4L * NOUT * H || s == 8L * NOUT * H || s == 2L * NOUT * H)
            w2 = d_in[i];
    }
    (void)out_size;

    k_detect<<<1, 1>>>(spk, w1, v1, w2);
    k_zero_out<<<(NOUT * T + 255) / 256, 256>>>((float*)d_out);
    k_v1T<<<dim3(H / 32, H / 32), dim3(32, 8)>>>(v1);
    k_packA<<<(GEMM_M * GEMM_K + 255) / 256, 256>>>(spk);
    k_packB<<<(H * GEMM_K + 255) / 256, 256>>>(w1);
    k_w2T<<<(NOUT * H + 255) / 256, 256>>>(w2);
    k_gemm<<<dim3(H / 128, GEMM_M / 64), 256>>>();
    k_gemm_check<<<16, 256>>>();
    k_gemm_fix<<<(T * H / 4 + 255) / 256, 256>>>();
    k_snn<<<NBLK, NTHR>>>((float*)d_out);
}

// round 10
// speedup vs baseline: 1.8393x; 1.2735x over previous
#include <cuda_runtime.h>
#include <cuda_bf16.h>
#include <cuda_fp16.h>
#include <cstdint>

#define H     4096
#define NIN   700
#define T     1000
#define NOUT  20
#define NG    1024           // u32 groups of 4 neurons
#define GPB   128            // groups per hidden block

#define GEMM_M 1024
#define GEMM_K 704
#define NBLK   9             // block 0 = readout, 1..8 = hidden
#define NTHR   128

// ---------------- device-global scratch ----------------
__device__ unsigned    g_v1T4[(size_t)(H + 1) * NG]; // packed v1T: [k][g] 4x int8; row 4096 = 0
__device__ signed char g_As8[GEMM_M * GEMM_K];
__device__ signed char g_Bs8[(size_t)H * GEMM_K];
__device__ int         g_inall[T * H];
__device__ int         g_w2Tp[(H + 1) * NOUT];       // w2T padded: row 4096 = 0
__device__ int         g_mask[6][H / 32];            // 6-slot ring of spike bitmasks
__device__ unsigned    g_bar_arrive;
__device__ unsigned    g_bar_gen;
__device__ int         g_dt[4];
__device__ int         g_bad;

// dtype codes: 0:f32 1:i32 2:i64 3:f64 4:bf16 5:f16
__device__ __forceinline__ int ldin(const void* p, long idx, int dt) {
    switch (dt) {
        case 0:  return (int)((const float*)p)[idx];
        case 1:  return ((const int*)p)[idx];
        case 2:  return (int)((const long long*)p)[idx];
        case 3:  return (int)((const double*)p)[idx];
        case 4:  return (int)__bfloat162float(((const __nv_bfloat16*)p)[idx]);
        default: return (int)__half2float(((const __half*)p)[idx]);
    }
}

__device__ __forceinline__ bool bf16ok(unsigned short h) {
    unsigned short a = h & 0x7FFF;
    return h == 0 || a == 0x3F80 || a == 0x4000 || a == 0x4040 || a == 0x4080 ||
           a == 0x40A0 || a == 0x40C0 || a == 0x40E0 || a == 0x4100;
}
__device__ __forceinline__ bool f16ok(unsigned short h) {
    unsigned short a = h & 0x7FFF;
    return h == 0 || a == 0x3C00 || a == 0x4000 || a == 0x4200 || a == 0x4400 ||
           a == 0x4500 || a == 0x4600 || a == 0x4700 || a == 0x4800;
}

__device__ int classify(const void* ptr) {
    const unsigned* p = (const unsigned*)ptr;
    const unsigned short* ph = (const unsigned short*)ptr;
    bool i64 = true;
    for (int i = 0; i < 32; i++) {
        int lo = (int)p[2 * i], hi = (int)p[2 * i + 1];
        bool sext = (hi == 0 && lo >= 0) || (hi == -1 && lo < 0);
        if (!(sext && lo >= -16 && lo <= 16)) { i64 = false; break; }
    }
    if (i64) return 2;
    bool f64 = true;
    for (int i = 0; i < 32; i++) {
        unsigned lo = p[2 * i], hi = p[2 * i + 1];
        unsigned ex = (hi >> 20) & 0x7FF;
        bool zero = (lo == 0 && (hi & 0x7FFFFFFFu) == 0);
        if (!(zero || (ex >= 1020 && ex <= 1026))) { f64 = false; break; }
    }
    if (f64) return 3;
    bool i32 = true;
    for (int i = 0; i < 64; i++) {
        int v = (int)p[i];
        if (v < -16 || v > 16) { i32 = false; break; }
    }
    if (i32) return 1;
    bool f32 = true;
    for (int i = 0; i < 64; i++)
        if (!(ph[2 * i] == 0 && bf16ok(ph[2 * i + 1]))) { f32 = false; break; }
    if (f32) return 0;
    bool b16 = true, anyEven = false;
    for (int i = 0; i < 128; i++) {
        if (!bf16ok(ph[i])) { b16 = false; break; }
        if ((i & 1) == 0 && ph[i] != 0) anyEven = true;
    }
    if (b16 && anyEven) return 4;
    bool h16 = true;
    for (int i = 0; i < 128; i++) if (!f16ok(ph[i])) { h16 = false; break; }
    if (h16) return 5;
    return 0;
}

__global__ void k_detect(const void* spk, const void* w1, const void* v1, const void* w2) {
    g_bad = 0;
    g_dt[0] = classify(spk);
    g_dt[1] = classify(w1);
    g_dt[2] = classify(v1);
    g_dt[3] = classify(w2);
}

__global__ void k_zero_out(float* out) {
    int i = blockIdx.x * blockDim.x + threadIdx.x;
    if (i < NOUT * T) out[i] = 0.0f;
}

// ---------------- conversion kernels ----------------
// v1 [h][k] -> g_v1T4[k][g] packed 4x int8 (byte i = v1[4g+i][k]); tile transpose
__global__ void k_v1T4(const void* v1) {
    __shared__ unsigned tile[32][33];
    const int dt = g_dt[2];
    int k0 = blockIdx.x * 32, g0 = blockIdx.y * 32;
    int tx = threadIdx.x, ty = threadIdx.y;
    for (int r = ty; r < 32; r += 8) {
        int gg = g0 + r;
        unsigned w = 0;
#pragma unroll
        for (int i = 0; i < 4; i++) {
            int v = ldin(v1, (long)(4 * gg + i) * H + (k0 + tx), dt);
            w |= ((unsigned)v & 0xFFu) << (8 * i);
        }
        tile[tx][r] = w;               // (k=k0+tx, g=g0+r)
    }
    __syncthreads();
    for (int r = ty; r < 32; r += 8)
        g_v1T4[(size_t)(k0 + r) * NG + (g0 + tx)] = tile[r][tx];
}

// zero pad rows (k = 4096)
__global__ void k_pad() {
    int i = blockIdx.x * blockDim.x + threadIdx.x;
    if (i < NG) g_v1T4[(size_t)H * NG + i] = 0u;
    if (i < NOUT) g_w2Tp[H * NOUT + i] = 0;
}

__global__ void k_packA(const void* spk) {
    int idx = blockIdx.x * blockDim.x + threadIdx.x;
    if (idx >= GEMM_M * GEMM_K) return;
    int t = idx / GEMM_K, i = idx % GEMM_K;
    int v = (t < T && i < NIN) ? ldin(spk, (long)t * NIN + i, g_dt[0]) : 0;
    g_As8[idx] = (signed char)v;
}

__global__ void k_packB(const void* w1) {
    int idx = blockIdx.x * blockDim.x + threadIdx.x;
    if (idx >= H * GEMM_K) return;
    int h = idx / GEMM_K, i = idx % GEMM_K;
    int v = (i < NIN) ? ldin(w1, (long)h * NIN + i, g_dt[1]) : 0;
    g_Bs8[idx] = (signed char)v;
}

__global__ void k_w2Tp(const void* w2) {
    int idx = blockIdx.x * blockDim.x + threadIdx.x;
    if (idx >= NOUT * H) return;
    int o = idx / H, k = idx % H;
    g_w2Tp[k * NOUT + o] = ldin(w2, (long)o * H + k, g_dt[3]);
}

// ---------------- int8 tensor-core GEMM (feed-forward currents) ----------------
__global__ void __launch_bounds__(256) k_gemm() {
    __shared__ signed char sA[64][32];
    __shared__ signed char sB[128][32];
    const int tid = threadIdx.x, lane = tid & 31, wid = tid >> 5;
    const int wm = wid & 1, wn = wid >> 1;
    const int mBase = blockIdx.y * 64, nBase = blockIdx.x * 128;

    int acc[2][4][4];
#pragma unroll
    for (int a = 0; a < 2; a++)
#pragma unroll
        for (int b = 0; b < 4; b++)
#pragma unroll
            for (int c = 0; c < 4; c++) acc[a][b][c] = 0;

    for (int k0 = 0; k0 < GEMM_K; k0 += 32) {
#pragma unroll
        for (int u = 0; u < 2; u++) {
            int w = tid + u * 256;
            int r = w >> 3, c = (w & 7) * 4;
            *(int*)&sA[r][c] = *(const int*)&g_As8[(mBase + r) * GEMM_K + k0 + c];
        }
#pragma unroll
        for (int u = 0; u < 4; u++) {
            int w = tid + u * 256;
            int r = w >> 3, c = (w & 7) * 4;
            *(int*)&sB[r][c] = *(const int*)&g_Bs8[(size_t)(nBase + r) * GEMM_K + k0 + c];
        }
        __syncthreads();

        int afrag[2][4];
#pragma unroll
        for (int mf = 0; mf < 2; mf++) {
            int r = wm * 32 + mf * 16 + (lane >> 2);
            int c = (lane & 3) * 4;
            afrag[mf][0] = *(const int*)&sA[r][c];
            afrag[mf][1] = *(const int*)&sA[r + 8][c];
            afrag[mf][2] = *(const int*)&sA[r][c + 16];
            afrag[mf][3] = *(const int*)&sA[r + 8][c + 16];
        }
        int bfrag[4][2];
#pragma unroll
        for (int nf = 0; nf < 4; nf++) {
            int col = wn * 32 + nf * 8 + (lane >> 2);
            int c = (lane & 3) * 4;
            bfrag[nf][0] = *(const int*)&sB[col][c];
            bfrag[nf][1] = *(const int*)&sB[col][c + 16];
        }
#pragma unroll
        for (int mf = 0; mf < 2; mf++)
#pragma unroll
            for (int nf = 0; nf < 4; nf++) {
                asm volatile(
                    "mma.sync.aligned.m16n8k32.row.col.s32.s8.s8.s32 "
                    "{%0,%1,%2,%3}, {%4,%5,%6,%7}, {%8,%9}, {%0,%1,%2,%3};"
                    : "+r"(acc[mf][nf][0]), "+r"(acc[mf][nf][1]),
                      "+r"(acc[mf][nf][2]), "+r"(acc[mf][nf][3])
                    : "r"(afrag[mf][0]), "r"(afrag[mf][1]),
                      "r"(afrag[mf][2]), "r"(afrag[mf][3]),
                      "r"(bfrag[nf][0]), "r"(bfrag[nf][1]));
            }
        __syncthreads();
    }
#pragma unroll
    for (int mf = 0; mf < 2; mf++) {
        int r0 = mBase + wm * 32 + mf * 16 + (lane >> 2);
#pragma unroll
        for (int nf = 0; nf < 4; nf++) {
            int c0 = nBase + wn * 32 + nf * 8 + (lane & 3) * 2;
            if (r0 < T) {
                g_inall[r0 * H + c0]     = acc[mf][nf][0];
                g_inall[r0 * H + c0 + 1] = acc[mf][nf][1];
            }
            if (r0 + 8 < T) {
                g_inall[(r0 + 8) * H + c0]     = acc[mf][nf][2];
                g_inall[(r0 + 8) * H + c0 + 1] = acc[mf][nf][3];
            }
        }
    }
}

__global__ void k_gemm_check() {
    int idx = blockIdx.x * blockDim.x + threadIdx.x;
    int t = (idx * 61) % T;
    int h = (idx * 97) % H;
    int acc = 0;
    for (int j = 0; j < GEMM_K / 4; j++)
        acc = __dp4a(*(const int*)&g_As8[t * GEMM_K + 4 * j],
                     *(const int*)&g_Bs8[(size_t)h * GEMM_K + 4 * j], acc);
    if (acc != g_inall[t * H + h]) g_bad = 1;
}

__global__ void k_gemm_fix() {
    if (g_bad == 0) return;
    int base = (blockIdx.x * blockDim.x + threadIdx.x) * 4;
    for (int e = 0; e < 4; e++) {
        int idx = base + e;
        if (idx >= T * H) return;
        int t = idx / H, h = idx % H;
        int acc = 0;
        for (int j = 0; j < GEMM_K / 4; j++)
            acc = __dp4a(*(const int*)&g_As8[t * GEMM_K + 4 * j],
                         *(const int*)&g_Bs8[(size_t)h * GEMM_K + 4 * j], acc);
        g_inall[idx] = acc;
    }
}

// ---------------- memory-order helpers ----------------
__device__ __forceinline__ unsigned atomAddAcqRel(unsigned* p, unsigned v) {
    unsigned old;
    asm volatile("atom.acq_rel.gpu.add.u32 %0, [%1], %2;" : "=r"(old) : "l"(p), "r"(v) : "memory");
    return old;
}
__device__ __forceinline__ unsigned ldAcqU(unsigned* p) {
    unsigned v;
    asm volatile("ld.acquire.gpu.u32 %0, [%1];" : "=r"(v) : "l"(p) : "memory");
    return v;
}
__device__ __forceinline__ int ldAcqI(const int* p) {
    int v;
    asm volatile("ld.acquire.gpu.s32 %0, [%1];" : "=r"(v) : "l"(p) : "memory");
    return v;
}
__device__ __forceinline__ void stRel(unsigned* p, unsigned v) {
    asm volatile("st.release.gpu.u32 [%0], %1;" :: "l"(p), "r"(v) : "memory");
}
__device__ __forceinline__ void gridBarrier(unsigned& myGen) {
    __syncthreads();
    if (threadIdx.x == 0) {
        myGen++;
        unsigned a = atomAddAcqRel(&g_bar_arrive, 1u);
        if (a == NBLK - 1) {
            stRel(&g_bar_arrive, 0u);
            atomAddAcqRel(&g_bar_gen, 1u);
        } else {
            while (ldAcqU(&g_bar_gen) != myGen) { __nanosleep(32); }
        }
    }
    __syncthreads();
}

// warp-collective: scan popcounts of 128 mask words -> exclusive bases + total
__device__ __forceinline__ void scan128(const int* m, int* b, int lane) {
    int c0 = __popc(m[4 * lane + 0]);
    int c1 = __popc(m[4 * lane + 1]);
    int c2 = __popc(m[4 * lane + 2]);
    int c3 = __popc(m[4 * lane + 3]);
    int s = c0 + c1 + c2 + c3;
    int incl = s;
#pragma unroll
    for (int d = 1; d < 32; d <<= 1) {
        int v = __shfl_up_sync(0xffffffffu, incl, d);
        if (lane >= d) incl += v;
    }
    int excl = incl - s;
    b[4 * lane + 0] = excl;
    b[4 * lane + 1] = excl + c0;
    b[4 * lane + 2] = excl + c0 + c1;
    b[4 * lane + 3] = excl + c0 + c1 + c2;
    if (lane == 31) b[128] = incl;
}

__device__ __forceinline__ void buildList16(const int* m, const int* b,
                                            unsigned short* list, int w) {
    unsigned mk = (unsigned)m[w];
    int p = b[w];
    int base = w << 5;
    while (mk) {
        int bit = __ffs(mk) - 1;
        list[p++] = (unsigned short)(base + bit);
        mk &= mk - 1;
    }
}

// ---------------- persistent loop: 3 steps per phase, ONE barrier per phase ----------------
// Phase p (steps 3p..3p+2): reads S_{3p-3..3p-1} (slots (3p+3+s)%6), gathers
// fb_{3p-2}, fb_{3p-1}, fb_{3p}, advances LIF 3 steps, publishes o_{3p..3p+2}
// (slots (3p+s)%6), readout emits rmem_{3p-2..3p}. Dependency depth = 3: exact.
__global__ void __launch_bounds__(NTHR, 1) k_snn(float* __restrict__ rout) {
    __shared__ unsigned short sL[3][H];     // 24 KB
    __shared__ int sM[3][128];
    __shared__ int sB[3][129];
    __shared__ int sPart[3][NOUT][6];       // readout partials (block 0)
    const int tid = threadIdx.x;
    const int cta = blockIdx.x;
    const int lane = tid & 31, wid = tid >> 5;
    const int g = (cta - 1) * GPB + tid;    // hidden group (cta>=1): neurons 4g..4g+3

    int memv[4] = {0, 0, 0, 0}, synv[4] = {0, 0, 0, 0};
    int oP2 = 0, oP1 = 0;                   // spike nibbles for steps t'-2, t'-1
    int rsyn = 0, rmem = 0;

    unsigned myGen = 0;
    if (tid == 0) myGen = ldAcqU(&g_bar_gen);
    for (int w = tid; w < 6 * 128; w += NTHR) ((int*)g_mask)[w] = 0;  // same value: benign
    __threadfence();
    gridBarrier(myGen);

    for (int p = 0; p < 334; p++) {
        const int tb = 3 * p;
        // ---- 1) read 3 masks ----
#pragma unroll
        for (int s = 0; s < 3; s++)
            sM[s][tid] = ldAcqI(&g_mask[(tb + 3 + s) % 6][tid]);
        __syncthreads();
        // ---- 2) scan (3 warps) ----
        if (wid < 3) scan128(sM[wid], sB[wid], lane);
        __syncthreads();
        const int K0 = sB[0][128], K1 = sB[1][128], K2 = sB[2][128];
        int Km = K0 > K1 ? K0 : K1; if (K2 > Km) Km = K2;
        const int Kpad = (Km + 3) & ~3;
        // ---- 3) build + pad lists ----
#pragma unroll
        for (int s = 0; s < 3; s++) {
            buildList16(sM[s], sB[s], sL[s], tid);
            for (int j = sB[s][128] + tid; j < Kpad; j += NTHR)
                sL[s][j] = (unsigned short)H;          // zero row
        }
        __syncthreads();

        if (cta > 0) {
            // ---- 4) inc rows (tb-2, tb-1, tb) ----
            int4 incv[3];
#pragma unroll
            for (int s = 0; s < 3; s++) {
                int tr = tb - 2 + s;
                incv[s] = (tr >= 0) ? *(const int4*)&g_inall[tr * H + 4 * g]
                                    : make_int4(0, 0, 0, 0);
            }
            // ---- 5) fused 3-stream gather, 4 neurons per thread via dp4a ----
            int acc[3][4];
#pragma unroll
            for (int s = 0; s < 3; s++)
#pragma unroll
                for (int i = 0; i < 4; i++) acc[s][i] = 0;
            for (int j = 0; j < Kpad; j += 4) {
#pragma unroll
                for (int u = 0; u < 4; u++) {
                    unsigned w0 = g_v1T4[(size_t)sL[0][j + u] * NG + g];
                    unsigned w1 = g_v1T4[(size_t)sL[1][j + u] * NG + g];
                    unsigned w2 = g_v1T4[(size_t)sL[2][j + u] * NG + g];
                    acc[0][0] = __dp4a((int)w0, 1, acc[0][0]);
                    acc[0][1] = __dp4a((int)w0, 0x100, acc[0][1]);
                    acc[0][2] = __dp4a((int)w0, 0x10000, acc[0][2]);
                    acc[0][3] = __dp4a((int)w0, 0x1000000, acc[0][3]);
                    acc[1][0] = __dp4a((int)w1, 1, acc[1][0]);
                    acc[1][1] = __dp4a((int)w1, 0x100, acc[1][1]);
                    acc[1][2] = __dp4a((int)w1, 0x10000, acc[1][2]);
                    acc[1][3] = __dp4a((int)w1, 0x1000000, acc[1][3]);
                    acc[2][0] = __dp4a((int)w2, 1, acc[2][0]);
                    acc[2][1] = __dp4a((int)w2, 0x100, acc[2][1]);
                    acc[2][2] = __dp4a((int)w2, 0x10000, acc[2][2]);
                    acc[2][3] = __dp4a((int)w2, 0x1000000, acc[2][3]);
                }
            }
            // ---- 6) LIF advance: 3 steps for 4 neurons ----
            int nib0 = 0, nib1 = 0, nib2 = 0;
            const int iA[4] = {incv[0].x, incv[0].y, incv[0].z, incv[0].w};
            const int iB[4] = {incv[1].x, incv[1].y, incv[1].z, incv[1].w};
            const int iC[4] = {incv[2].x, incv[2].y, incv[2].z, incv[2].w};
#pragma unroll
            for (int i = 0; i < 4; i++) {
                int m = memv[i], s = synv[i];
                const int om2 = (oP2 >> i) & 1, om1 = (oP1 >> i) & 1;
                // step A: syn_{tb-2}, mem_{tb-1}
                s = s - (s >> 4) + iA[i] + acc[0][i];
                int m0 = om2 ? 0 : m;
                m = m0 - (m0 >> 3) + s;
                // step B: syn_{tb-1}; o_{tb}; mem_{tb}
                s = s - (s >> 4) + iB[i] + acc[1][i];
                int m1 = om1 ? 0 : m;
                int o0 = (m1 > 1) ? 1 : 0;
                m = m1 - (m1 >> 3) + s;
                // step C: syn_{tb}; o_{tb+1}; mem_{tb+1}; o_{tb+2}
                s = s - (s >> 4) + iC[i] + acc[2][i];
                int m2 = o0 ? 0 : m;
                int o1 = (m2 > 1) ? 1 : 0;
                m = m2 - (m2 >> 3) + s;
                int m3 = o1 ? 0 : m;
                int o2 = (m3 > 1) ? 1 : 0;
                memv[i] = m; synv[i] = s;
                nib0 |= o0 << i; nib1 |= o1 << i; nib2 |= o2 << i;
            }
            oP2 = nib1; oP1 = nib2;
            // ---- 7) publish: assemble 32-bit words from 8-thread groups ----
            const int sh = 4 * (tid & 7);
            int v0 = nib0 << sh, v1 = nib1 << sh, v2 = nib2 << sh;
#pragma unroll
            for (int d = 1; d < 8; d <<= 1) {
                v0 |= __shfl_xor_sync(0xffffffffu, v0, d);
                v1 |= __shfl_xor_sync(0xffffffffu, v1, d);
                v2 |= __shfl_xor_sync(0xffffffffu, v2, d);
            }
            if ((tid & 7) == 0) {
                const int wI = g >> 3;
                g_mask[tb % 6][wI]       = v0;
                g_mask[(tb + 1) % 6][wI] = v1;
                g_mask[(tb + 2) % 6][wI] = v2;
                __threadfence();
            }
        } else {
            // ---- readout block: rc_s = w2 @ S_{tb-3+s}; emit rmem_{tb-2+s} ----
            if (tid < 120) {
                const int o = tid % NOUT, q = tid / NOUT;   // 6 partials per output
                int pa = 0, pb = 0, pc = 0;
                for (int j = q; j < Kpad; j += 6) {
                    pa += g_w2Tp[(int)sL[0][j] * NOUT + o];
                    pb += g_w2Tp[(int)sL[1][j] * NOUT + o];
                    pc += g_w2Tp[(int)sL[2][j] * NOUT + o];
                }
                sPart[0][o][q] = pa; sPart[1][o][q] = pb; sPart[2][o][q] = pc;
            }
            __syncthreads();
            if (tid < NOUT) {
#pragma unroll
                for (int s = 0; s < 3; s++) {
                    int rc = sPart[s][tid][0] + sPart[s][tid][1] + sPart[s][tid][2] +
                             sPart[s][tid][3] + sPart[s][tid][4] + sPart[s][tid][5];
                    rsyn = rsyn - (rsyn >> 4) + rc;
                    rmem = rmem - (rmem >> 3) + rsyn;
                    int t = tb - 2 + s;
                    if (t >= 0) rout[tid * T + t] = (float)rmem;
                }
            }
        }
        // ---- 8) one barrier per 3 steps ----
        gridBarrier(myGen);
    }
}

// ---------------- launch ----------------
extern "C" void kernel_launch(void* const* d_in, const int* in_sizes, int n_in,
                              void* d_out, int out_size) {
    const void *spk = d_in[0], *w1 = d_in[1], *v1 = d_in[2], *w2 = d_in[3];
    for (int i = 0; i < n_in; i++) {
        long s = in_sizes[i];
        if (s == (long)T * NIN || s == 4L * T * NIN || s == 8L * T * NIN || s == 2L * T * NIN)
            spk = d_in[i];
        else if (s == (long)H * NIN || s == 4L * H * NIN || s == 8L * H * NIN || s == 2L * H * NIN)
            w1 = d_in[i];
        else if (s == (long)H * H || s == 4L * H * H || s == 8L * H * H || s == 2L * H * H)
            v1 = d_in[i];
        else if (s == (long)NOUT * H || s == 4L * NOUT * H || s == 8L * NOUT * H || s == 2L * NOUT * H)
            w2 = d_in[i];
    }
    (void)out_size;

    k_detect<<<1, 1>>>(spk, w1, v1, w2);
    k_zero_out<<<(NOUT * T + 255) / 256, 256>>>((float*)d_out);
    k_v1T4<<<dim3(H / 32, NG / 32), dim3(32, 8)>>>(v1);
    k_pad<<<(NG + 255) / 256, 256>>>();
    k_packA<<<(GEMM_M * GEMM_K + 255) / 256, 256>>>(spk);
    k_packB<<<(H * GEMM_K + 255) / 256, 256>>>(w1);
    k_w2Tp<<<(NOUT * H + 255) / 256, 256>>>(w2);
    k_gemm<<<dim3(H / 128, GEMM_M / 64), 256>>>();
    k_gemm_check<<<16, 256>>>();
    k_gemm_fix<<<(T * H / 4 + 255) / 256, 256>>>();
    k_snn<<<NBLK, NTHR>>>((float*)d_out);
}